// round 8
// baseline (speedup 1.0000x reference)
#include <cuda_runtime.h>
#include <cuda_bf16.h>

// GCNConv (1 in/out feature, self-loops, symmetric norm) + sigmoid.
// out[d] = sigmoid( dinv[d]*( SUM_{e:dst=d} dinv[src]*x[src]*W + dinv[d]*x[d]*W ) + b )
//
// Measured model: both edge passes are L1tex-wavefront-bound (~1 wf/cyc/SM).
// Per edge: degree = 1 RED wf, scatter = 1 gather wf + 1 RED wf  =>  ~100M wf
// => ~375us chip floor. This round fuses all phases into ONE persistent
// kernel with software global barriers to eliminate launch gaps/tails.

#define MAXN 1048576
#define NB   444          // 148 SMs x 3 blocks (co-resident by launch bounds)
#define TPB  512

__device__ int   g_ideg[MAXN];   // in-degree; ==0 at entry (restored by phase 4)
__device__ float g_y[MAXN];      // x * W * rsqrt(deg)
__device__ float g_S[MAXN];      // edge accumulator; ==0 at entry (restored)
__device__ int   g_cnt;          // monotonic barrier arrivals (never reset)
__device__ int   g_rel;          // monotonic barrier releases (never reset)

// Global barrier: monotonic counters, replay-safe without resets.
// All blocks read `base` (=g_rel at launch entry) BEFORE their first arrival;
// no release can happen until every block has arrived once, so the read races
// nothing. Completer of barrier k bumps g_rel; waiters spin for base+k.
__device__ __forceinline__ void gbar(int base, int k) {
    __syncthreads();
    if (threadIdx.x == 0) {
        __threadfence();                       // publish this block's writes
        int t = atomicAdd(&g_cnt, 1) + 1;
        if ((t % NB) == 0) {
            atomicAdd(&g_rel, 1);              // release barrier k
        } else {
            while (atomicAdd(&g_rel, 0) < base + k) __nanosleep(64);
        }
        __threadfence();                       // acquire released writes
    }
    __syncthreads();
}

__global__ __launch_bounds__(TPB, 3) void k_fused(
    const float* __restrict__ x,
    const int*   __restrict__ src,
    const int*   __restrict__ dst,
    const float* __restrict__ W,
    const float* __restrict__ b,
    float*       __restrict__ out,
    int n, int e)
{
    const int tid  = threadIdx.x;
    const int gtid = blockIdx.x * TPB + tid;
    const int nthr = NB * TPB;

    int base = 0;
    if (tid == 0) base = atomicAdd(&g_rel, 0);   // launch-entry release count

    // ---- Phase 1: degree (16 edges/thread-iter, front-batched loads) ----
    const int e16 = e / 16;
    for (int i = gtid; i < e16; i += nthr) {
        const int4* p = reinterpret_cast<const int4*>(dst) + (size_t)i * 4;
        int4 a = p[0];
        int4 bb = p[1];
        int4 c = p[2];
        int4 d = p[3];
        atomicAdd(&g_ideg[a.x], 1);
        atomicAdd(&g_ideg[a.y], 1);
        atomicAdd(&g_ideg[a.z], 1);
        atomicAdd(&g_ideg[a.w], 1);
        atomicAdd(&g_ideg[bb.x], 1);
        atomicAdd(&g_ideg[bb.y], 1);
        atomicAdd(&g_ideg[bb.z], 1);
        atomicAdd(&g_ideg[bb.w], 1);
        atomicAdd(&g_ideg[c.x], 1);
        atomicAdd(&g_ideg[c.y], 1);
        atomicAdd(&g_ideg[c.z], 1);
        atomicAdd(&g_ideg[c.w], 1);
        atomicAdd(&g_ideg[d.x], 1);
        atomicAdd(&g_ideg[d.y], 1);
        atomicAdd(&g_ideg[d.z], 1);
        atomicAdd(&g_ideg[d.w], 1);
    }
    for (int t = e16 * 16 + gtid; t < e; t += nthr)
        atomicAdd(&g_ideg[dst[t]], 1);

    gbar(base, 1);

    // ---- Phase 2: y = x*W*rsqrt(deg+1) ----
    const float w = __ldg(W);
    const int n4 = n / 4;
    for (int i = gtid; i < n4; i += nthr) {
        int4   dg = reinterpret_cast<const int4*>(g_ideg)[i];
        float4 xv = reinterpret_cast<const float4*>(x)[i];
        float4 yv;
        yv.x = xv.x * w * rsqrtf((float)(dg.x + 1));
        yv.y = xv.y * w * rsqrtf((float)(dg.y + 1));
        yv.z = xv.z * w * rsqrtf((float)(dg.z + 1));
        yv.w = xv.w * w * rsqrtf((float)(dg.w + 1));
        reinterpret_cast<float4*>(g_y)[i] = yv;
    }
    for (int t = n4 * 4 + gtid; t < n; t += nthr)
        g_y[t] = x[t] * w * rsqrtf((float)(g_ideg[t] + 1));

    gbar(base, 2);

    // ---- Phase 3: scatter  S[dst] += y[src]  (8 edges/thread-iter) ----
    const int e8 = e / 8;
    for (int i = gtid; i < e8; i += nthr) {
        const int4* ps = reinterpret_cast<const int4*>(src) + (size_t)i * 2;
        const int4* pd = reinterpret_cast<const int4*>(dst) + (size_t)i * 2;
        int4 s0 = ps[0];
        int4 s1 = ps[1];
        int4 d0 = pd[0];
        int4 d1 = pd[1];
        float v0 = __ldg(&g_y[s0.x]);
        float v1 = __ldg(&g_y[s0.y]);
        float v2 = __ldg(&g_y[s0.z]);
        float v3 = __ldg(&g_y[s0.w]);
        float v4 = __ldg(&g_y[s1.x]);
        float v5 = __ldg(&g_y[s1.y]);
        float v6 = __ldg(&g_y[s1.z]);
        float v7 = __ldg(&g_y[s1.w]);
        atomicAdd(&g_S[d0.x], v0);
        atomicAdd(&g_S[d0.y], v1);
        atomicAdd(&g_S[d0.z], v2);
        atomicAdd(&g_S[d0.w], v3);
        atomicAdd(&g_S[d1.x], v4);
        atomicAdd(&g_S[d1.y], v5);
        atomicAdd(&g_S[d1.z], v6);
        atomicAdd(&g_S[d1.w], v7);
    }
    for (int t = e8 * 8 + gtid; t < e; t += nthr)
        atomicAdd(&g_S[dst[t]], __ldg(&g_y[src[t]]));

    gbar(base, 3);

    // ---- Phase 4: out = sigmoid(dinv*(S+y)+b); restore ideg=0, S=0 ----
    const float bias = __ldg(b);
    for (int i = gtid; i < n4; i += nthr) {
        int4   dg = reinterpret_cast<const int4*>(g_ideg)[i];
        float4 sv = reinterpret_cast<const float4*>(g_S)[i];
        float4 yv = reinterpret_cast<const float4*>(g_y)[i];
        float4 o;
        float z0 = rsqrtf((float)(dg.x + 1)) * (sv.x + yv.x) + bias;
        float z1 = rsqrtf((float)(dg.y + 1)) * (sv.y + yv.y) + bias;
        float z2 = rsqrtf((float)(dg.z + 1)) * (sv.z + yv.z) + bias;
        float z3 = rsqrtf((float)(dg.w + 1)) * (sv.w + yv.w) + bias;
        o.x = 1.0f / (1.0f + __expf(-z0));
        o.y = 1.0f / (1.0f + __expf(-z1));
        o.z = 1.0f / (1.0f + __expf(-z2));
        o.w = 1.0f / (1.0f + __expf(-z3));
        reinterpret_cast<float4*>(out)[i] = o;
        reinterpret_cast<int4*>(g_ideg)[i]  = make_int4(0, 0, 0, 0);
        reinterpret_cast<float4*>(g_S)[i]   = make_float4(0.f, 0.f, 0.f, 0.f);
    }
    for (int t = n4 * 4 + gtid; t < n; t += nthr) {
        float z = rsqrtf((float)(g_ideg[t] + 1)) * (g_S[t] + g_y[t]) + bias;
        out[t] = 1.0f / (1.0f + __expf(-z));
        g_ideg[t] = 0;
        g_S[t] = 0.0f;
    }
}

// ---------------------------------------------------------------------------
extern "C" void kernel_launch(void* const* d_in, const int* in_sizes, int n_in,
                              void* d_out, int out_size) {
    const float* x    = (const float*)d_in[0];
    const int*   eidx = (const int*)  d_in[1];
    const float* W    = (const float*)d_in[2];
    const float* b    = (const float*)d_in[3];
    float* out = (float*)d_out;

    int n = in_sizes[0];
    int e = in_sizes[1] / 2;
    const int* src = eidx;
    const int* dst = eidx + e;

    k_fused<<<NB, TPB>>>(x, src, dst, W, b, out, n, e);
}

// round 9
// speedup vs baseline: 1.4066x; 1.4066x over previous
#include <cuda_runtime.h>
#include <cuda_bf16.h>

// GCNConv (1 in/out feature, self-loops, symmetric norm) + sigmoid.
// out[d] = sigmoid( dinv[d]*( SUM_{e:dst=d} dinv[src]*x[src]*W + dinv[d]*x[d]*W ) + b )
//
// Model (confirmed over R1-R8): edge passes are L1tex-wavefront / LTS-RMW
// bound: scatter 66M wf -> ~232us, degree 34M wf -> ~128us; chip floor ~375us.
// R8's persistent fusion regressed (occupancy cap + barrier straggler spread);
// this is the best-measured discrete structure: R1 edge-kernel shape
// (4 edges/thread, TPB 256 - best scatter: 232.5us) + R7 node-side trims
// (no zero pass: __device__ globals start zero, k_final restores zeros).

#define MAXN 1048576

__device__ int   g_ideg[MAXN];   // in-degree; ==0 at entry (restored by k_final)
__device__ float g_y[MAXN];      // x * W * rsqrt(deg)
__device__ float g_S[MAXN];      // edge accumulator; ==0 at entry (restored)

// ---------------------------------------------------------------------------
// Degree: 4 edges/thread (one int4 coalesced read), 4 REDs (L2-resident).
__global__ void k_degree(const int* __restrict__ dst, int e4, int e) {
    int i = blockIdx.x * blockDim.x + threadIdx.x;
    if (i < e4) {
        int4 d = reinterpret_cast<const int4*>(dst)[i];
        atomicAdd(&g_ideg[d.x], 1);
        atomicAdd(&g_ideg[d.y], 1);
        atomicAdd(&g_ideg[d.z], 1);
        atomicAdd(&g_ideg[d.w], 1);
    }
    int t = e4 * 4 + i;
    if (i < (e - e4 * 4)) {
        atomicAdd(&g_ideg[dst[t]], 1);
    }
}

// ---------------------------------------------------------------------------
// Per-node: y = x*W*rsqrt(deg+1).  (S already zero; restored by k_final.)
__global__ void k_node(const float* __restrict__ x,
                       const float* __restrict__ W, int n4) {
    int i = blockIdx.x * blockDim.x + threadIdx.x;
    if (i < n4) {
        float w  = __ldg(W);
        int4  dg = reinterpret_cast<const int4*>(g_ideg)[i];
        float4 xv = reinterpret_cast<const float4*>(x)[i];
        float4 yv;
        yv.x = xv.x * w * rsqrtf((float)(dg.x + 1));
        yv.y = xv.y * w * rsqrtf((float)(dg.y + 1));
        yv.z = xv.z * w * rsqrtf((float)(dg.z + 1));
        yv.w = xv.w * w * rsqrtf((float)(dg.w + 1));
        reinterpret_cast<float4*>(g_y)[i] = yv;
    }
}
__global__ void k_node_tail(const float* __restrict__ x,
                            const float* __restrict__ W, int n4, int n) {
    int i = n4 * 4 + blockIdx.x * blockDim.x + threadIdx.x;
    if (i < n) {
        g_y[i] = x[i] * __ldg(W) * rsqrtf((float)(g_ideg[i] + 1));
    }
}

// ---------------------------------------------------------------------------
// Scatter: 4 edges/thread (R1 shape - best measured). Gathers issued before
// REDs for MLP=4 within the thread; warp-level interleave covers the rest.
__global__ void k_scatter(const int* __restrict__ src,
                          const int* __restrict__ dst, int e4, int e) {
    int i = blockIdx.x * blockDim.x + threadIdx.x;
    if (i < e4) {
        int4 s = reinterpret_cast<const int4*>(src)[i];
        int4 d = reinterpret_cast<const int4*>(dst)[i];
        float va = __ldg(&g_y[s.x]);
        float vb = __ldg(&g_y[s.y]);
        float vc = __ldg(&g_y[s.z]);
        float vd = __ldg(&g_y[s.w]);
        atomicAdd(&g_S[d.x], va);
        atomicAdd(&g_S[d.y], vb);
        atomicAdd(&g_S[d.z], vc);
        atomicAdd(&g_S[d.w], vd);
    }
    int t = e4 * 4 + i;
    if (i < (e - e4 * 4)) {
        atomicAdd(&g_S[dst[t]], __ldg(&g_y[src[t]]));
    }
}

// ---------------------------------------------------------------------------
// Finalize: out = sigmoid(rsqrt(deg+1)*(S + y) + b); then restore the
// ideg==0 / S==0 entry invariant for the next graph replay (streaming
// stores, hidden under 20%-utilized DRAM).
__global__ void k_final(float* __restrict__ out,
                        const float* __restrict__ b, int n4) {
    int i = blockIdx.x * blockDim.x + threadIdx.x;
    if (i < n4) {
        float bb = __ldg(b);
        int4   dg = reinterpret_cast<const int4*>(g_ideg)[i];
        float4 sv = reinterpret_cast<const float4*>(g_S)[i];
        float4 yv = reinterpret_cast<const float4*>(g_y)[i];
        float4 o;
        float z0 = rsqrtf((float)(dg.x + 1)) * (sv.x + yv.x) + bb;
        float z1 = rsqrtf((float)(dg.y + 1)) * (sv.y + yv.y) + bb;
        float z2 = rsqrtf((float)(dg.z + 1)) * (sv.z + yv.z) + bb;
        float z3 = rsqrtf((float)(dg.w + 1)) * (sv.w + yv.w) + bb;
        o.x = 1.0f / (1.0f + __expf(-z0));
        o.y = 1.0f / (1.0f + __expf(-z1));
        o.z = 1.0f / (1.0f + __expf(-z2));
        o.w = 1.0f / (1.0f + __expf(-z3));
        reinterpret_cast<float4*>(out)[i] = o;
        reinterpret_cast<int4*>(g_ideg)[i]  = make_int4(0, 0, 0, 0);
        reinterpret_cast<float4*>(g_S)[i]   = make_float4(0.f, 0.f, 0.f, 0.f);
    }
}
__global__ void k_final_tail(float* __restrict__ out,
                             const float* __restrict__ b, int n4, int n) {
    int i = n4 * 4 + blockIdx.x * blockDim.x + threadIdx.x;
    if (i < n) {
        float z = rsqrtf((float)(g_ideg[i] + 1)) * (g_S[i] + g_y[i]) + __ldg(b);
        out[i] = 1.0f / (1.0f + __expf(-z));
        g_ideg[i] = 0;
        g_S[i] = 0.0f;
    }
}

// ---------------------------------------------------------------------------
extern "C" void kernel_launch(void* const* d_in, const int* in_sizes, int n_in,
                              void* d_out, int out_size) {
    const float* x    = (const float*)d_in[0];
    const int*   eidx = (const int*)  d_in[1];
    const float* W    = (const float*)d_in[2];
    const float* b    = (const float*)d_in[3];
    float* out = (float*)d_out;

    int n = in_sizes[0];
    int e = in_sizes[1] / 2;
    const int* src = eidx;
    const int* dst = eidx + e;

    int n4 = n / 4;
    int e4 = e / 4;

    const int TPB = 256;
    int gn4 = (n4 + TPB - 1) / TPB;
    int ge4 = (e4 + TPB - 1) / TPB;

    k_degree <<<ge4, TPB>>>(dst, e4, e);
    k_node   <<<gn4, TPB>>>(x, W, n4);
    if (n % 4) k_node_tail<<<1, 256>>>(x, W, n4, n);
    k_scatter<<<ge4, TPB>>>(src, dst, e4, e);
    k_final  <<<gn4, TPB>>>(out, b, n4);
    if (n % 4) k_final_tail<<<1, 256>>>(out, b, n4, n);
}

// round 10
// speedup vs baseline: 1.4080x; 1.0010x over previous
#include <cuda_runtime.h>
#include <cuda_bf16.h>

// GCNConv (1 in/out feature, self-loops, symmetric norm) + sigmoid.
// out[d] = sigmoid( dinv[d]*( SUM_{e:dst=d} dinv[src]*x[src]*W + dinv[d]*x[d]*W ) + b )
//
// Validated model (R1-R9):
//   k_scatter: 66M L1tex/LTS random ops, LTS cap ~170/cyc      -> ~232us
//   k_degree : 32M REDs, ATOMG-issue floor 148/cyc              -> ~127us
//   node/final/gaps                                             -> ~25us
// R10: TPB 128 on edge kernels (measured trend 512->236us, 256->232.5us;
// smaller CTAs reduce multi-CTA L1tex-queue spread). Convergence probe.

#define MAXN 1048576

__device__ int   g_ideg[MAXN];   // in-degree; ==0 at entry (restored by k_final)
__device__ float g_y[MAXN];      // x * W * rsqrt(deg)
__device__ float g_S[MAXN];      // edge accumulator; ==0 at entry (restored)

// ---------------------------------------------------------------------------
// Degree: 4 edges/thread (one int4 coalesced read), 4 REDs (L2-resident).
__global__ void k_degree(const int* __restrict__ dst, int e4, int e) {
    int i = blockIdx.x * blockDim.x + threadIdx.x;
    if (i < e4) {
        int4 d = reinterpret_cast<const int4*>(dst)[i];
        atomicAdd(&g_ideg[d.x], 1);
        atomicAdd(&g_ideg[d.y], 1);
        atomicAdd(&g_ideg[d.z], 1);
        atomicAdd(&g_ideg[d.w], 1);
    }
    int t = e4 * 4 + i;
    if (i < (e - e4 * 4)) {
        atomicAdd(&g_ideg[dst[t]], 1);
    }
}

// ---------------------------------------------------------------------------
// Per-node: y = x*W*rsqrt(deg+1).  (S already zero; restored by k_final.)
__global__ void k_node(const float* __restrict__ x,
                       const float* __restrict__ W, int n4) {
    int i = blockIdx.x * blockDim.x + threadIdx.x;
    if (i < n4) {
        float w  = __ldg(W);
        int4  dg = reinterpret_cast<const int4*>(g_ideg)[i];
        float4 xv = reinterpret_cast<const float4*>(x)[i];
        float4 yv;
        yv.x = xv.x * w * rsqrtf((float)(dg.x + 1));
        yv.y = xv.y * w * rsqrtf((float)(dg.y + 1));
        yv.z = xv.z * w * rsqrtf((float)(dg.z + 1));
        yv.w = xv.w * w * rsqrtf((float)(dg.w + 1));
        reinterpret_cast<float4*>(g_y)[i] = yv;
    }
}
__global__ void k_node_tail(const float* __restrict__ x,
                            const float* __restrict__ W, int n4, int n) {
    int i = n4 * 4 + blockIdx.x * blockDim.x + threadIdx.x;
    if (i < n) {
        g_y[i] = x[i] * __ldg(W) * rsqrtf((float)(g_ideg[i] + 1));
    }
}

// ---------------------------------------------------------------------------
// Scatter: 4 edges/thread. Gathers issued before REDs (MLP=4 per thread).
__global__ void k_scatter(const int* __restrict__ src,
                          const int* __restrict__ dst, int e4, int e) {
    int i = blockIdx.x * blockDim.x + threadIdx.x;
    if (i < e4) {
        int4 s = reinterpret_cast<const int4*>(src)[i];
        int4 d = reinterpret_cast<const int4*>(dst)[i];
        float va = __ldg(&g_y[s.x]);
        float vb = __ldg(&g_y[s.y]);
        float vc = __ldg(&g_y[s.z]);
        float vd = __ldg(&g_y[s.w]);
        atomicAdd(&g_S[d.x], va);
        atomicAdd(&g_S[d.y], vb);
        atomicAdd(&g_S[d.z], vc);
        atomicAdd(&g_S[d.w], vd);
    }
    int t = e4 * 4 + i;
    if (i < (e - e4 * 4)) {
        atomicAdd(&g_S[dst[t]], __ldg(&g_y[src[t]]));
    }
}

// ---------------------------------------------------------------------------
// Finalize: out = sigmoid(rsqrt(deg+1)*(S + y) + b); restore ideg==0 / S==0
// entry invariant for the next graph replay (streaming stores, DRAM ~20%).
__global__ void k_final(float* __restrict__ out,
                        const float* __restrict__ b, int n4) {
    int i = blockIdx.x * blockDim.x + threadIdx.x;
    if (i < n4) {
        float bb = __ldg(b);
        int4   dg = reinterpret_cast<const int4*>(g_ideg)[i];
        float4 sv = reinterpret_cast<const float4*>(g_S)[i];
        float4 yv = reinterpret_cast<const float4*>(g_y)[i];
        float4 o;
        float z0 = rsqrtf((float)(dg.x + 1)) * (sv.x + yv.x) + bb;
        float z1 = rsqrtf((float)(dg.y + 1)) * (sv.y + yv.y) + bb;
        float z2 = rsqrtf((float)(dg.z + 1)) * (sv.z + yv.z) + bb;
        float z3 = rsqrtf((float)(dg.w + 1)) * (sv.w + yv.w) + bb;
        o.x = 1.0f / (1.0f + __expf(-z0));
        o.y = 1.0f / (1.0f + __expf(-z1));
        o.z = 1.0f / (1.0f + __expf(-z2));
        o.w = 1.0f / (1.0f + __expf(-z3));
        reinterpret_cast<float4*>(out)[i] = o;
        reinterpret_cast<int4*>(g_ideg)[i]  = make_int4(0, 0, 0, 0);
        reinterpret_cast<float4*>(g_S)[i]   = make_float4(0.f, 0.f, 0.f, 0.f);
    }
}
__global__ void k_final_tail(float* __restrict__ out,
                             const float* __restrict__ b, int n4, int n) {
    int i = n4 * 4 + blockIdx.x * blockDim.x + threadIdx.x;
    if (i < n) {
        float z = rsqrtf((float)(g_ideg[i] + 1)) * (g_S[i] + g_y[i]) + __ldg(b);
        out[i] = 1.0f / (1.0f + __expf(-z));
        g_ideg[i] = 0;
        g_S[i] = 0.0f;
    }
}

// ---------------------------------------------------------------------------
extern "C" void kernel_launch(void* const* d_in, const int* in_sizes, int n_in,
                              void* d_out, int out_size) {
    const float* x    = (const float*)d_in[0];
    const int*   eidx = (const int*)  d_in[1];
    const float* W    = (const float*)d_in[2];
    const float* b    = (const float*)d_in[3];
    float* out = (float*)d_out;

    int n = in_sizes[0];
    int e = in_sizes[1] / 2;
    const int* src = eidx;
    const int* dst = eidx + e;

    int n4 = n / 4;
    int e4 = e / 4;

    const int TPBN = 256;   // node-side kernels
    const int TPBE = 128;   // edge kernels: probe (512->236us, 256->232.5us)
    int gn4 = (n4 + TPBN - 1) / TPBN;
    int ge4 = (e4 + TPBE - 1) / TPBE;

    k_degree <<<ge4, TPBE>>>(dst, e4, e);
    k_node   <<<gn4, TPBN>>>(x, W, n4);
    if (n % 4) k_node_tail<<<1, 256>>>(x, W, n4, n);
    k_scatter<<<ge4, TPBE>>>(src, dst, e4, e);
    k_final  <<<gn4, TPBN>>>(out, b, n4);
    if (n % 4) k_final_tail<<<1, 256>>>(out, b, n4, n);
}